// round 5
// baseline (speedup 1.0000x reference)
#include <cuda_runtime.h>

// LTU_5918464934238: binary-threshold GEMV.
// out[i] = (W[i]·x + count(W[i]<0) < 2457.6) ? 0 : 1
//
// R5: contiguous 8-row slab per block (DRAM page locality per SM stream)
// + __ldcs evict-first streaming loads for the read-once 128 MB W.
// x read via __ldg (L1-resident). One barrier per row, as in R1 (covered
// by ~7 concurrent blocks per SM).

#define LTU_THREADS 256
#define LTU_VECS    1024                 // float4 per row
#define LTU_RPB     8                    // contiguous rows per block

__device__ __forceinline__ float4 ldcs4(const float4* p) {
    return __ldcs(p);
}

__global__ __launch_bounds__(LTU_THREADS)
void ltu_kernel(const float* __restrict__ x,
                const float* __restrict__ W,
                float* __restrict__ out)
{
    __shared__ float wsum[2][LTU_THREADS / 32];

    const int tid  = threadIdx.x;
    const int lane = tid & 31;
    const int warp = tid >> 5;
    const int row0 = blockIdx.x * LTU_RPB;

    const float4* __restrict__ xv = reinterpret_cast<const float4*>(x);

    // x per-thread slice: 4 float4, L1-resident after first block on the SM.
    const float4 v0 = __ldg(xv + tid);
    const float4 v1 = __ldg(xv + tid + 256);
    const float4 v2 = __ldg(xv + tid + 512);
    const float4 v3 = __ldg(xv + tid + 768);

    const float4* __restrict__ Wb =
        reinterpret_cast<const float4*>(W) + (size_t)row0 * LTU_VECS;

    #pragma unroll 1
    for (int r = 0; r < LTU_RPB; r++) {
        const float4* __restrict__ Wr = Wb + (size_t)r * LTU_VECS;

        // Front-batched streaming loads (evict-first).
        const float4 w0 = ldcs4(Wr + tid);
        const float4 w1 = ldcs4(Wr + tid + 256);
        const float4 w2 = ldcs4(Wr + tid + 512);
        const float4 w3 = ldcs4(Wr + tid + 768);

        float a0 = 0.f, a1 = 0.f, a2 = 0.f, a3 = 0.f;
        a0 = fmaf(w0.x, v0.x, a0); a1 = fmaf(w0.y, v0.y, a1);
        a2 = fmaf(w0.z, v0.z, a2); a3 = fmaf(w0.w, v0.w, a3);
        a0 = fmaf(w1.x, v1.x, a0); a1 = fmaf(w1.y, v1.y, a1);
        a2 = fmaf(w1.z, v1.z, a2); a3 = fmaf(w1.w, v1.w, a3);
        a0 = fmaf(w2.x, v2.x, a0); a1 = fmaf(w2.y, v2.y, a1);
        a2 = fmaf(w2.z, v2.z, a2); a3 = fmaf(w2.w, v2.w, a3);
        a0 = fmaf(w3.x, v3.x, a0); a1 = fmaf(w3.y, v3.y, a1);
        a2 = fmaf(w3.z, v3.z, a2); a3 = fmaf(w3.w, v3.w, a3);

        const unsigned c =
            (__float_as_uint(w0.x) >> 31) + (__float_as_uint(w0.y) >> 31) +
            (__float_as_uint(w0.z) >> 31) + (__float_as_uint(w0.w) >> 31) +
            (__float_as_uint(w1.x) >> 31) + (__float_as_uint(w1.y) >> 31) +
            (__float_as_uint(w1.z) >> 31) + (__float_as_uint(w1.w) >> 31) +
            (__float_as_uint(w2.x) >> 31) + (__float_as_uint(w2.y) >> 31) +
            (__float_as_uint(w2.z) >> 31) + (__float_as_uint(w2.w) >> 31) +
            (__float_as_uint(w3.x) >> 31) + (__float_as_uint(w3.y) >> 31) +
            (__float_as_uint(w3.z) >> 31) + (__float_as_uint(w3.w) >> 31);

        float t = (a0 + a1) + (a2 + a3) + (float)c;

        #pragma unroll
        for (int o = 16; o > 0; o >>= 1)
            t += __shfl_xor_sync(0xffffffffu, t, o);
        if (lane == 0) wsum[r & 1][warp] = t;

        __syncthreads();   // wsum visible; ping-pong allows skew of 1 row

        if (warp == 0) {
            float s = (lane < (LTU_THREADS / 32)) ? wsum[r & 1][lane] : 0.f;
            #pragma unroll
            for (int o = (LTU_THREADS / 64); o > 0; o >>= 1)
                s += __shfl_xor_sync(0xffffffffu, s, o);
            if (lane == 0) {
                const float tau_base = 0.6f * 4096.0f;  // 2457.60009765625
                out[row0 + r] = (s < tau_base) ? 0.0f : 1.0f;
            }
        }
    }
}

extern "C" void kernel_launch(void* const* d_in, const int* in_sizes, int n_in,
                              void* d_out, int out_size)
{
    const float* x = (const float*)d_in[0];
    const float* W = (const float*)d_in[1];
    if (n_in >= 2 && in_sizes[0] > in_sizes[1]) {
        x = (const float*)d_in[1];
        W = (const float*)d_in[0];
    }
    float* out = (float*)d_out;
    const int rows = out_size;            // 8192

    const int grid = rows / LTU_RPB;      // 1024 blocks, 8 contiguous rows each
    ltu_kernel<<<grid, LTU_THREADS>>>(x, W, out);
}

// round 6
// speedup vs baseline: 1.1351x; 1.1351x over previous
#include <cuda_runtime.h>

// LTU_5918464934238: binary-threshold GEMV, persistent + software-pipelined.
// out[i] = (W[i]·x + count(W[i]<0) < 2457.6) ? 0 : 1
//
// R6: 512 thr/block, 3 blocks/SM (75% occ), W double-buffered in registers so
// row j+1's LDG.128s are in flight BEFORE row j's reduce/barrier -> the load
// pipe never drains. x kept in registers (L1-resident __ldg), no staging.

#define LTU_THREADS 512
#define LTU_NWARP   (LTU_THREADS / 32)
#define LTU_VECS    1024                 // float4 per row
#define LTU_GRID    444                  // 148 SMs * 3 blocks

__device__ __forceinline__ float ltu_dot8(const float4 w0, const float4 w1,
                                          const float4 v0, const float4 v1)
{
    float a0 = 0.f, a1 = 0.f, a2 = 0.f, a3 = 0.f;
    a0 = fmaf(w0.x, v0.x, a0); a1 = fmaf(w0.y, v0.y, a1);
    a2 = fmaf(w0.z, v0.z, a2); a3 = fmaf(w0.w, v0.w, a3);
    a0 = fmaf(w1.x, v1.x, a0); a1 = fmaf(w1.y, v1.y, a1);
    a2 = fmaf(w1.z, v1.z, a2); a3 = fmaf(w1.w, v1.w, a3);
    const unsigned c =
        (__float_as_uint(w0.x) >> 31) + (__float_as_uint(w0.y) >> 31) +
        (__float_as_uint(w0.z) >> 31) + (__float_as_uint(w0.w) >> 31) +
        (__float_as_uint(w1.x) >> 31) + (__float_as_uint(w1.y) >> 31) +
        (__float_as_uint(w1.z) >> 31) + (__float_as_uint(w1.w) >> 31);
    return (a0 + a1) + (a2 + a3) + (float)c;
}

__device__ __forceinline__ void ltu_finish(float t, float* wsum,
                                           float* __restrict__ outp,
                                           int lane, int warp)
{
    #pragma unroll
    for (int o = 16; o > 0; o >>= 1)
        t += __shfl_xor_sync(0xffffffffu, t, o);
    if (lane == 0) wsum[warp] = t;
    __syncthreads();
    if (warp == 0) {
        float s = (lane < LTU_NWARP) ? wsum[lane] : 0.0f;
        #pragma unroll
        for (int o = LTU_NWARP / 2; o > 0; o >>= 1)
            s += __shfl_xor_sync(0xffffffffu, s, o);
        if (lane == 0) {
            const float tau_base = 0.6f * 4096.0f;   // 2457.60009765625
            *outp = (s < tau_base) ? 0.0f : 1.0f;
        }
    }
}

__global__ __launch_bounds__(LTU_THREADS, 3)
void ltu_kernel(const float* __restrict__ x,
                const float* __restrict__ W,
                float* __restrict__ out,
                int rows)
{
    __shared__ float wsum[2][LTU_NWARP];

    const int tid  = threadIdx.x;
    const int lane = tid & 31;
    const int warp = tid >> 5;
    const int bid  = blockIdx.x;

    const float4* __restrict__ xv = reinterpret_cast<const float4*>(x);
    const float4* __restrict__ Wv = reinterpret_cast<const float4*>(W);

    // x per-thread slice (constant across rows): 2 float4 in registers.
    const float4 v0 = __ldg(xv + tid);
    const float4 v1 = __ldg(xv + tid + LTU_THREADS);

    const int nloc = (rows > bid) ? (rows - 1 - bid) / LTU_GRID + 1 : 0;

    float4 a0, a1, b0, b1;
    if (nloc > 0) {
        const size_t base = (size_t)bid * LTU_VECS;
        a0 = Wv[base + tid];
        a1 = Wv[base + tid + LTU_THREADS];
    }

    for (int j = 0; j < nloc; j += 2) {
        // Prefetch row j+1 BEFORE row j's reduce: loads in flight across
        // the shuffle/barrier dead window.
        if (j + 1 < nloc) {
            const size_t base = (size_t)(bid + (j + 1) * LTU_GRID) * LTU_VECS;
            b0 = Wv[base + tid];
            b1 = Wv[base + tid + LTU_THREADS];
        }

        ltu_finish(ltu_dot8(a0, a1, v0, v1), wsum[0],
                   out + bid + (size_t)j * LTU_GRID, lane, warp);

        if (j + 1 >= nloc) break;

        // Prefetch row j+2 before row j+1's reduce.
        if (j + 2 < nloc) {
            const size_t base = (size_t)(bid + (j + 2) * LTU_GRID) * LTU_VECS;
            a0 = Wv[base + tid];
            a1 = Wv[base + tid + LTU_THREADS];
        }

        ltu_finish(ltu_dot8(b0, b1, v0, v1), wsum[1],
                   out + bid + (size_t)(j + 1) * LTU_GRID, lane, warp);
    }
    // wsum ping-pong: warp0's trailing read of wsum[k] is protected by the
    // next row's __syncthreads before wsum[k] is rewritten (2-row spacing).
}

extern "C" void kernel_launch(void* const* d_in, const int* in_sizes, int n_in,
                              void* d_out, int out_size)
{
    const float* x = (const float*)d_in[0];
    const float* W = (const float*)d_in[1];
    if (n_in >= 2 && in_sizes[0] > in_sizes[1]) {
        x = (const float*)d_in[1];
        W = (const float*)d_in[0];
    }
    float* out = (float*)d_out;
    const int rows = out_size;            // 8192

    ltu_kernel<<<LTU_GRID, LTU_THREADS>>>(x, W, out, rows);
}